// round 8
// baseline (speedup 1.0000x reference)
#include <cuda_runtime.h>
#include <math.h>
#include <float.h>
#include <stdint.h>

#define NTOK  16384
#define BSZ   4
#define SEQ   4096
#define DIM   2048
#define NEXP  64
#define TOPK  8
#define BM    64     // tokens per block
#define KC    32     // K chunk width
#define NTHREADS 128

#define FTZ_MIN 1.17549435e-38f   // FLT_MIN: fp32 normal threshold (FTZ cutoff)

__device__ float g_cnt[BSZ * NEXP];
__device__ float g_ssum[BSZ * NEXP];

__global__ void gate_zero() {
    int i = threadIdx.x;
    if (i < BSZ * NEXP) { g_cnt[i] = 0.f; g_ssum[i] = 0.f; }
}

__global__ __launch_bounds__(NTHREADS) void gate_main(
    const float* __restrict__ x, const float* __restrict__ w,
    const float* __restrict__ bias, float* __restrict__ out)
{
    __shared__ float xs[BM][KC + 1];
    __shared__ float ws[NEXP][KC + 1];
    __shared__ float lg[BM][NEXP + 1];
    __shared__ float s_max[BM];
    __shared__ float s_inv[BM];
    __shared__ float s_cnt[NEXP];

    const int tid = threadIdx.x;
    const int et  = tid & 15;   // expert group: experts et*4 .. et*4+3
    const int tt  = tid >> 4;   // token group : tokens  tt*8 .. tt*8+7
    const int base = blockIdx.x * BM;

    float acc[8][4];
    #pragma unroll
    for (int i = 0; i < 8; i++)
        #pragma unroll
        for (int j = 0; j < 4; j++) acc[i][j] = 0.f;

    const float* xb = x + (size_t)base * DIM;

    for (int kc = 0; kc < DIM; kc += KC) {
        // cooperative load: 64x32 x-chunk and 64x32 w-chunk (float4, coalesced)
        #pragma unroll
        for (int it = 0; it < 4; it++) {
            int idx = tid + it * NTHREADS;       // 0..511 float4 slots
            int r = idx >> 3;
            int c = (idx & 7) << 2;
            float4 v = *(const float4*)(xb + (size_t)r * DIM + kc + c);
            xs[r][c] = v.x; xs[r][c+1] = v.y; xs[r][c+2] = v.z; xs[r][c+3] = v.w;
            float4 u = *(const float4*)(w + (size_t)r * DIM + kc + c);
            ws[r][c] = u.x; ws[r][c+1] = u.y; ws[r][c+2] = u.z; ws[r][c+3] = u.w;
        }
        __syncthreads();

        // exact fp32 fmaf chain, K strictly ascending, one accumulator per output
        #pragma unroll
        for (int k = 0; k < KC; k++) {
            float wv[4], xv[8];
            #pragma unroll
            for (int j = 0; j < 4; j++) wv[j] = ws[et * 4 + j][k];
            #pragma unroll
            for (int i = 0; i < 8; i++) xv[i] = xs[tt * 8 + i][k];
            #pragma unroll
            for (int i = 0; i < 8; i++)
                #pragma unroll
                for (int j = 0; j < 4; j++)
                    acc[i][j] = fmaf(xv[i], wv[j], acc[i][j]);
        }
        __syncthreads();
    }

    // logits + bias -> smem
    #pragma unroll
    for (int j = 0; j < 4; j++) {
        float b = bias[et * 4 + j];
        #pragma unroll
        for (int i = 0; i < 8; i++)
            lg[tt * 8 + i][et * 4 + j] = acc[i][j] + b;
    }
    if (tid < NEXP) s_cnt[tid] = 0.f;
    __syncthreads();

    // per-token softmax (FTZ) + top-8 on SCORES, ties -> lower index (lax.top_k)
    if (tid < BM) {
        const int t = tid;
        float m = -FLT_MAX;
        for (int e = 0; e < NEXP; e++) m = fmaxf(m, lg[t][e]);

        // pass 1: FTZ-flushed exp, sum
        float sum = 0.f;
        for (int e = 0; e < NEXP; e++) {
            float s = expf(lg[t][e] - m);
            if (s < FTZ_MIN) s = 0.f;            // fp32 underflow -> exactly 0
            sum += s;
        }
        float inv_sum = 1.f / sum;

        // pass 2: final scores q = flush(s/sum); top-8 by (q desc, index asc)
        float bv[TOPK]; int bi[TOPK];
        #pragma unroll
        for (int r = 0; r < TOPK; r++) { bv[r] = -FLT_MAX; bi[r] = 0; }

        for (int e = 0; e < NEXP; e++) {
            float s = expf(lg[t][e] - m);
            if (s < FTZ_MIN) s = 0.f;
            float q = s * inv_sum;               // sum ~ 1; flush quotient too
            if (q < FTZ_MIN) q = 0.f;
            if (q > bv[TOPK - 1]) {              // strict >: equal keeps earlier (lower) idx
                int p = TOPK - 1;
                while (p > 0 && q > bv[p - 1]) {
                    bv[p] = bv[p - 1]; bi[p] = bi[p - 1]; p--;
                }
                bv[p] = q; bi[p] = e;
            }
        }
        s_max[t] = m;
        s_inv[t] = inv_sum;

        // normalized weights: q_r / (sum q_r + 1e-20)
        float den = 1e-20f;
        #pragma unroll
        for (int r = 0; r < TOPK; r++) den += bv[r];
        float inv = 1.f / den;

        const int token = base + t;
        #pragma unroll
        for (int r = 0; r < TOPK; r++)
            out[(size_t)token * TOPK + r] = (float)bi[r];
        #pragma unroll
        for (int r = 0; r < TOPK; r++)
            out[(size_t)NTOK * TOPK + (size_t)token * TOPK + r] = bv[r] * inv;
        #pragma unroll
        for (int r = 0; r < TOPK; r++)
            atomicAdd(&s_cnt[bi[r]], 1.f);
    }
    __syncthreads();

    // per-expert column sums of (flushed) softmax scores over this block's tokens
    if (tid < NEXP) {
        const int e = tid;
        float cs = 0.f;
        for (int t = 0; t < BM; t++) {
            float s = expf(lg[t][e] - s_max[t]);
            if (s < FTZ_MIN) s = 0.f;
            float q = s * s_inv[t];
            if (q < FTZ_MIN) q = 0.f;
            cs += q;
        }
        const int b = base / SEQ;
        atomicAdd(&g_ssum[b * NEXP + e], cs);
        atomicAdd(&g_cnt[b * NEXP + e], s_cnt[e]);
    }
}

__global__ void gate_finalize(float* __restrict__ out) {
    __shared__ float red[256];
    const int i = threadIdx.x;
    // aux = mean_b sum_e (cnt/(SEQ*K/E)) * (ssum/SEQ)
    float v = (g_cnt[i] * (1.f / 512.f)) * (g_ssum[i] * (1.f / 4096.f));
    red[i] = v;
    __syncthreads();
    for (int s = 128; s > 0; s >>= 1) {
        if (i < s) red[i] += red[i + s];
        __syncthreads();
    }
    if (i == 0) out[2 * NTOK * TOPK] = red[0] * (1.f / BSZ);
}

extern "C" void kernel_launch(void* const* d_in, const int* in_sizes, int n_in,
                              void* d_out, int out_size) {
    const float* x    = (const float*)d_in[0];   // [4,4096,2048] f32
    const float* wgt  = (const float*)d_in[1];   // [64,2048]     f32
    const float* bias = (const float*)d_in[2];   // [64]          f32
    float* out = (float*)d_out;                  // [idx 131072][w 131072][aux 1]

    gate_zero<<<1, 256>>>();
    gate_main<<<NTOK / BM, NTHREADS>>>(x, wgt, bias, out);
    gate_finalize<<<1, 256>>>(out);
}